// round 3
// baseline (speedup 1.0000x reference)
#include <cuda_runtime.h>

// Focal cross-entropy, N rows x 2 classes, scalar-sum output. Single kernel:
// block partials -> double atomicAdd -> fenced last-block writes out & resets state.
// inputs: d_in[0] = pred [N,2] f32, d_in[1] = gold [N] f32. out: 1 f32.

__device__ double g_acc = 0.0;
__device__ unsigned int g_done = 0u;

__device__ __forceinline__ float row_loss(float p0, float p1, float g) {
    // 2-class identity: d = p1-p0, t = exp(-|d|), L = log(1+t)
    //   -lp(hi)=L, -lp(lo)=|d|+L ; prb(hi)=1/(1+t), prb(lo)=t/(1+t)
    //   focal0=prb1^2, focal1=prb0^2
    float d   = p1 - p0;
    float ad  = fabsf(d);
    float t   = __expf(-ad);                 // MUFU.EX2
    float s   = 1.0f + t;
    float L   = __logf(s);                   // MUFU.LG2
    float inv = __fdividef(1.0f, s);         // MUFU.RCP
    float pr_hi = inv;
    float pr_lo = t * inv;

    bool pos = (d >= 0.0f);
    float nlp0 = pos ? (ad + L) : L;         // -log_softmax[0]
    float nlp1 = pos ? L : (ad + L);         // -log_softmax[1]
    float pr0  = pos ? pr_lo : pr_hi;
    float pr1  = pos ? pr_hi : pr_lo;

    float oh1 = (g >= 0.5f) ? 0.25f : 0.0f;
    float oh0 = (1.0f - oh1) * 0.75f;

    return oh0 * nlp0 * (pr1 * pr1) + oh1 * nlp1 * (pr0 * pr0);
}

__global__ void __launch_bounds__(256)
fl_fused_kernel(const float4* __restrict__ pred4,  // [N/2] float4 (2 rows each)
                const float4* __restrict__ gold4,  // [N/4] float4
                const float*  __restrict__ pred,
                const float*  __restrict__ gold,
                long long n4, long long n,
                float* __restrict__ out,
                unsigned int nblocks)
{
    long long i = (long long)blockIdx.x * blockDim.x + threadIdx.x;
    float acc = 0.0f;
    if (i < n4) {
        float4 g  = gold4[i];
        float4 pa = pred4[2 * i];       // rows 4i, 4i+1
        float4 pb = pred4[2 * i + 1];   // rows 4i+2, 4i+3
        acc  = row_loss(pa.x, pa.y, g.x);
        acc += row_loss(pa.z, pa.w, g.y);
        acc += row_loss(pb.x, pb.y, g.z);
        acc += row_loss(pb.z, pb.w, g.w);
    }

    // tail rows (n % 4), handled by thread 0 of block 0 (no-op for N = 2^24)
    if (blockIdx.x == 0 && threadIdx.x == 0) {
        for (long long r = n4 * 4; r < n; r++)
            acc += row_loss(pred[2 * r], pred[2 * r + 1], gold[r]);
    }

    // warp reduce
    #pragma unroll
    for (int off = 16; off > 0; off >>= 1)
        acc += __shfl_down_sync(0xFFFFFFFFu, acc, off);

    __shared__ float warp_sums[8];
    int lane = threadIdx.x & 31;
    int wid  = threadIdx.x >> 5;
    if (lane == 0) warp_sums[wid] = acc;
    __syncthreads();

    if (wid == 0) {
        float v = (lane < 8) ? warp_sums[lane] : 0.0f;
        #pragma unroll
        for (int off = 4; off > 0; off >>= 1)
            v += __shfl_down_sync(0xFFFFFFFFu, v, off);

        if (lane == 0) {
            atomicAdd(&g_acc, (double)v);
            __threadfence();
            unsigned int prev = atomicAdd(&g_done, 1u);
            if (prev == nblocks - 1u) {
                // all blocks' atomics are visible (each fenced before counter inc)
                out[0] = (float)g_acc;   // CORR = 1.0
                g_acc  = 0.0;            // reset for next (deterministic) replay
                g_done = 0u;
                __threadfence();
            }
        }
    }
}

extern "C" void kernel_launch(void* const* d_in, const int* in_sizes, int n_in,
                              void* d_out, int out_size)
{
    const float* pred = (const float*)d_in[0];
    const float* gold = (const float*)d_in[1];
    float* out = (float*)d_out;

    long long n  = in_sizes[1];      // rows (gold element count)
    long long n4 = n >> 2;

    int threads = 256;
    long long blocks = (n4 + threads - 1) / threads;
    if (blocks < 1) blocks = 1;

    fl_fused_kernel<<<(unsigned)blocks, threads>>>(
        (const float4*)pred, (const float4*)gold, pred, gold,
        n4, n, out, (unsigned)blocks);
}